// round 8
// baseline (speedup 1.0000x reference)
#include <cuda_runtime.h>

#define G       37
#define NPATCH  (G * G)          // 1369
#define D       768
#define NCUE    5
#define STOK    (NCUE + NPATCH)  // 1374
#define BATCH   128
#define EPSN    1e-12f

#define TPB     128              // 1 patch per thread
#define PTILE   128
#define NTILE   11               // ceil(1369/128)
#define DC      32               // dims per pipeline stage
#define NS      (D / DC)         // 24 stages
#define F4ROW   (DC / 4)         // 8 float4 per row-stage
#define STAGE_F4 (PTILE * F4ROW) // 1024 float4 = 16KB/buffer

// packed argmax scratch: high 32 = orderable sim key, low 32 = ~idx (lowest idx
// wins ties). Zero at module load; the per-batch finisher block resets both
// arrays after consuming them, so every graph replay is deterministic.
__device__ unsigned long long g_best[BATCH * NCUE];
__device__ int                g_done[BATCH];

__device__ __forceinline__ unsigned f2key(float f) {
    unsigned u = __float_as_uint(f);
    return (u & 0x80000000u) ? ~u : (u | 0x80000000u);
}
__device__ __forceinline__ void fma2(unsigned long long& d, unsigned long long a,
                                     unsigned long long b) {
    asm volatile("fma.rn.f32x2 %0, %1, %2, %0;" : "+l"(d) : "l"(a), "l"(b));
}
__device__ __forceinline__ void lds_v2u64(unsigned long long& lo, unsigned long long& hi,
                                          unsigned addr) {
    asm volatile("ld.shared.v2.u64 {%0, %1}, [%2];" : "=l"(lo), "=l"(hi) : "r"(addr));
}
__device__ __forceinline__ void cp16(unsigned dst, const void* src) {
    asm volatile("cp.async.cg.shared.global [%0], [%1], 16;" :: "r"(dst), "l"(src)
                 : "memory");
}

// ---------------------------------------------------------------------------
// Fused kernel: R4 argmax pipeline (unchanged — measured at the DRAM ceiling),
// then the LAST block to finish each batch performs that batch's gather +
// normalize inline, hidden under the other batches' argmax work.
// ---------------------------------------------------------------------------
__global__ __launch_bounds__(TPB, 4) void fused_kernel(const float* __restrict__ tokens,
                                                       float* __restrict__ out) {
    __shared__ float4 stage_buf[2][STAGE_F4];           // 32 KB
    __shared__ float  cue_sm[NCUE * D];                 // 15 KB
    __shared__ unsigned long long warp_best[TPB / 32][NCUE];
    __shared__ int    roi_idx[NCUE];
    __shared__ int    is_last;

    const int b    = blockIdx.y;
    const int t    = threadIdx.x;
    const int lane = t & 31;
    const int warp = t >> 5;
    const float* base  = tokens + (size_t)b * STOK * D;
    const float* patch = base + NCUE * D;
    const unsigned sb0 = (unsigned)__cvta_generic_to_shared(&stage_buf[0][0]);
    const int p0 = blockIdx.x * PTILE;

    // ---- R4 argmax (unchanged) ------------------------------------------
    const int seg = lane & 7;
    const char* gsrc[8];
    unsigned    sdst[8];
#pragma unroll
    for (int q = 0; q < 8; q++) {
        const int R    = warp * 32 + q * 4 + (lane >> 3);
        const int pidx = min(p0 + R, NPATCH - 1);       // tail clamp (idempotent)
        gsrc[q] = (const char*)(patch + (size_t)pidx * D) + seg * 16;
        sdst[q] = sb0 + (unsigned)((R * F4ROW + (seg ^ (R & 7))) * 16);
    }

#define ISSUE_STAGE(s, bufsel)                                                  \
    do {                                                                        \
        const unsigned _bo = (bufsel) ? (unsigned)(STAGE_F4 * 16) : 0u;         \
        const int _go = (s) * (DC * 4);                                         \
        _Pragma("unroll")                                                       \
        for (int _q = 0; _q < 8; _q++) cp16(sdst[_q] + _bo, gsrc[_q] + _go);    \
        asm volatile("cp.async.commit_group;" ::: "memory");                    \
    } while (0)

    ISSUE_STAGE(0, 0);
    ISSUE_STAGE(1, 1);

    {   // cues -> smem (contiguous)
        const float4* cg = (const float4*)base;
        float4* cs = (float4*)cue_sm;
        for (int i = t; i < NCUE * D / 4; i += TPB) cs[i] = cg[i];
    }
    __syncthreads();

    unsigned long long acc[NCUE][2];
#pragma unroll
    for (int c = 0; c < NCUE; c++) { acc[c][0] = 0ull; acc[c][1] = 0ull; }

    const unsigned rbase0 = sb0 + (unsigned)(t * F4ROW * 16);
    const unsigned cbase  = (unsigned)__cvta_generic_to_shared(cue_sm);

    for (int s = 0; s < NS; s++) {
        if (s < NS - 1) asm volatile("cp.async.wait_group 1;" ::: "memory");
        else            asm volatile("cp.async.wait_group 0;" ::: "memory");
        __syncwarp();

        const unsigned rb = rbase0 + ((s & 1) ? (unsigned)(STAGE_F4 * 16) : 0u);
        const unsigned cb = cbase + (unsigned)(s * DC * 4);
#pragma unroll
        for (int j4 = 0; j4 < F4ROW; j4++) {
            unsigned long long plo, phi;
            lds_v2u64(plo, phi, rb + (unsigned)((j4 ^ (t & 7)) * 16));
#pragma unroll
            for (int c = 0; c < NCUE; c++) {
                unsigned long long qlo, qhi;
                lds_v2u64(qlo, qhi, cb + (unsigned)(c * D * 4 + j4 * 16));
                fma2(acc[c][0], plo, qlo);
                fma2(acc[c][1], phi, qhi);
            }
        }
        __syncwarp();
        if (s + 2 < NS) ISSUE_STAGE(s + 2, s & 1);
    }
#undef ISSUE_STAGE

    const int pidx = min(p0 + t, NPATCH - 1);
    const unsigned lowbits = 0xFFFFFFFFu - (unsigned)pidx;
    unsigned long long key[NCUE];
#pragma unroll
    for (int c = 0; c < NCUE; c++) {
        float a0 = __uint_as_float((unsigned)(acc[c][0] & 0xFFFFFFFFull));
        float a1 = __uint_as_float((unsigned)(acc[c][0] >> 32));
        float a2 = __uint_as_float((unsigned)(acc[c][1] & 0xFFFFFFFFull));
        float a3 = __uint_as_float((unsigned)(acc[c][1] >> 32));
        float sim = (a0 + a1) + (a2 + a3);
        key[c] = ((unsigned long long)f2key(sim) << 32) | lowbits;
    }
#pragma unroll
    for (int c = 0; c < NCUE; c++)
#pragma unroll
        for (int o = 16; o; o >>= 1) {
            unsigned long long other = __shfl_xor_sync(0xffffffffu, key[c], o);
            key[c] = (other > key[c]) ? other : key[c];
        }
    if (lane == 0)
#pragma unroll
        for (int c = 0; c < NCUE; c++) warp_best[warp][c] = key[c];
    __syncthreads();
    if (t < NCUE) {
        unsigned long long m = warp_best[0][t];
#pragma unroll
        for (int w = 1; w < TPB / 32; w++)
            m = (warp_best[w][t] > m) ? warp_best[w][t] : m;
        atomicMax(&g_best[b * NCUE + t], m);
    }
    __syncthreads();

    // ---- finisher election ----------------------------------------------
    if (t == 0) {
        __threadfence();                         // release our atomicMax results
        const int prev = atomicAdd(&g_done[b], 1);
        is_last = (prev == NTILE - 1) ? 1 : 0;
    }
    __syncthreads();
    if (!is_last) return;
    __threadfence();                             // acquire all blocks' results

    // ---- gather + normalize for batch b (hidden under other batches) ----
    if (t < NCUE) {
        const unsigned long long k = __ldcg(&g_best[b * NCUE + t]);
        roi_idx[t] = (int)(0xFFFFFFFFu - (unsigned)(k & 0xFFFFFFFFull));
        g_best[b * NCUE + t] = 0ull;             // reset for next replay
    }
    if (t == 0) g_done[b] = 0;                   // reset for next replay
    __syncthreads();

    // 4 warps cover 10 tokens; cue tokens come straight from cue_sm.
    for (int tok = warp; tok < 2 * NCUE; tok += TPB / 32) {
        float4 v[6];

        if (tok < NCUE) {
            const float4* row = (const float4*)(cue_sm + tok * D);
#pragma unroll
            for (int k = 0; k < 6; k++) v[k] = row[lane + 32 * k];
        } else {
            const int idx = roi_idx[tok - NCUE];
            const int h = idx / G, w = idx % G;
            const float4* prow[9];
            float msk[9];
            float cnt = 0.0f;
#pragma unroll
            for (int dr = -1; dr <= 1; dr++)
#pragma unroll
                for (int dc = -1; dc <= 1; dc++) {
                    const int k2 = (dr + 1) * 3 + (dc + 1);
                    const int rr = h + dr, cc = w + dc;
                    const bool ok = (rr >= 0) & (rr < G) & (cc >= 0) & (cc < G);
                    const int rcl = min(max(rr, 0), G - 1);
                    const int ccl = min(max(cc, 0), G - 1);
                    prow[k2] = (const float4*)(patch + (size_t)(rcl * G + ccl) * D);
                    msk[k2]  = ok ? 1.0f : 0.0f;
                    cnt += msk[k2];
                }
            const float inv = 1.0f / cnt;
#pragma unroll
            for (int k = 0; k < 6; k++) v[k] = make_float4(0.f, 0.f, 0.f, 0.f);
#pragma unroll
            for (int r = 0; r < 9; r++) {
                const float m = msk[r];
#pragma unroll
                for (int k = 0; k < 6; k++) {
                    const float4 x = prow[r][lane + 32 * k];
                    v[k].x = fmaf(m, x.x, v[k].x);
                    v[k].y = fmaf(m, x.y, v[k].y);
                    v[k].z = fmaf(m, x.z, v[k].z);
                    v[k].w = fmaf(m, x.w, v[k].w);
                }
            }
#pragma unroll
            for (int k = 0; k < 6; k++) {
                v[k].x *= inv; v[k].y *= inv; v[k].z *= inv; v[k].w *= inv;
            }
        }

        float ss = 0.0f;
#pragma unroll
        for (int k = 0; k < 6; k++)
            ss += v[k].x * v[k].x + v[k].y * v[k].y +
                  v[k].z * v[k].z + v[k].w * v[k].w;
#pragma unroll
        for (int o = 16; o > 0; o >>= 1) ss += __shfl_xor_sync(0xffffffffu, ss, o);

        const float scale = 1.0f / fmaxf(sqrtf(ss), EPSN);
        float4* orow = (float4*)(out + ((size_t)b * 10 + tok) * D);
#pragma unroll
        for (int k = 0; k < 6; k++) {
            float4 vv = v[k];
            vv.x *= scale; vv.y *= scale; vv.z *= scale; vv.w *= scale;
            orow[lane + 32 * k] = vv;
        }
    }
}

extern "C" void kernel_launch(void* const* d_in, const int* in_sizes, int n_in,
                              void* d_out, int out_size) {
    const float* tokens = (const float*)d_in[0];
    float* out = (float*)d_out;

    fused_kernel<<<dim3(NTILE, BATCH), TPB>>>(tokens, out);
}

// round 9
// speedup vs baseline: 1.1580x; 1.1580x over previous
#include <cuda_runtime.h>

#define G       37
#define NPATCH  (G * G)          // 1369
#define D       768
#define NCUE    5
#define STOK    (NCUE + NPATCH)  // 1374
#define BATCH   128
#define EPSN    1e-12f

#define TPB     128              // 1 patch per thread
#define PTILE   128
#define NTILE   11               // ceil(1369/128)
#define DC      16               // dims per pipeline stage
#define NS      (D / DC)         // 48 stages
#define NBUF    4                // 4-deep ring, 3 stages in flight
#define F4ROW   (DC / 4)         // 4 float4 per row-stage
#define STAGE_F4 (PTILE * F4ROW) // 512 float4 = 8KB per buffer
#define STAGE_B  (STAGE_F4 * 16) // 8192

// packed argmax scratch: high 32 = orderable sim key, low 32 = ~idx (lowest idx
// wins ties). Zero-init at module load; gather_kernel resets after reading so
// every graph replay is deterministic.
__device__ unsigned long long g_best[BATCH * NCUE];

__device__ __forceinline__ unsigned f2key(float f) {
    unsigned u = __float_as_uint(f);
    return (u & 0x80000000u) ? ~u : (u | 0x80000000u);
}
__device__ __forceinline__ void fma2(unsigned long long& d, unsigned long long a,
                                     unsigned long long b) {
    asm volatile("fma.rn.f32x2 %0, %1, %2, %0;" : "+l"(d) : "l"(a), "l"(b));
}
__device__ __forceinline__ void lds_v2u64(unsigned long long& lo, unsigned long long& hi,
                                          unsigned addr) {
    asm volatile("ld.shared.v2.u64 {%0, %1}, [%2];" : "=l"(lo), "=l"(hi) : "r"(addr));
}
__device__ __forceinline__ void cp16(unsigned dst, const void* src) {
    asm volatile("cp.async.cg.shared.global [%0], [%1], 16;" :: "r"(dst), "l"(src)
                 : "memory");
}

// ---------------------------------------------------------------------------
// Kernel 1: per-(batch,cue) argmax over patch dot-products.
// R4 structure (1 patch/thread, warp-self-contained staging) but with a
// 4-deep cp.async ring (DC=16, wait_group 2): 3 stages in flight per warp
// raises per-SM bytes-in-flight 64KB -> ~96KB at unchanged smem/occupancy,
// covering the queueing-inflated DRAM latency that capped R4 at 5.85 TB/s.
// Swizzle unit = j ^ ((R>>1)&3): conflict-free reads (verified per 8-lane
// phase at 64B rows) and contiguous-512B conflict-free writes.
// ---------------------------------------------------------------------------
__global__ __launch_bounds__(TPB, 4) void argmax_kernel(const float* __restrict__ tokens) {
    __shared__ float4 stage_buf[NBUF][STAGE_F4];        // 32 KB
    __shared__ float  cue_sm[NCUE * D];                 // 15 KB
    __shared__ unsigned long long warp_best[TPB / 32][NCUE];

    const int b    = blockIdx.y;
    const int t    = threadIdx.x;
    const int lane = t & 31;
    const int warp = t >> 5;
    const float* base  = tokens + (size_t)b * STOK * D;
    const float* patch = base + NCUE * D;
    const unsigned sb0 = (unsigned)__cvta_generic_to_shared(&stage_buf[0][0]);
    const int p0 = blockIdx.x * PTILE;

    // Copy descriptors: instr q (0..3) stages rows R = 32w + 8q + (lane>>2),
    // 16B segment lane&3 — each warp-instr writes one contiguous 512B span.
    const int seg = lane & 3;
    const char* gsrc[4];
    unsigned    sdst[4];
#pragma unroll
    for (int q = 0; q < 4; q++) {
        const int R    = warp * 32 + q * 8 + (lane >> 2);
        const int pidx = min(p0 + R, NPATCH - 1);       // tail clamp (idempotent)
        gsrc[q] = (const char*)(patch + (size_t)pidx * D) + seg * 16;
        sdst[q] = sb0 + (unsigned)(R * 64 + ((seg ^ ((R >> 1) & 3)) * 16));
    }

#define ISSUE_STAGE(s)                                                          \
    do {                                                                        \
        const unsigned _bo = (unsigned)(((s) & (NBUF - 1)) * STAGE_B);          \
        const int _go = (s) * (DC * 4);                                         \
        _Pragma("unroll")                                                       \
        for (int _q = 0; _q < 4; _q++) cp16(sdst[_q] + _bo, gsrc[_q] + _go);    \
        asm volatile("cp.async.commit_group;" ::: "memory");                    \
    } while (0)

    // Kick DRAM with 3 stages before staging cues.
    ISSUE_STAGE(0);
    ISSUE_STAGE(1);
    ISSUE_STAGE(2);

    {   // cues = tokens[b, 0:5, :] (contiguous) -> smem
        const float4* cg = (const float4*)base;
        float4* cs = (float4*)cue_sm;
        for (int i = t; i < NCUE * D / 4; i += TPB) cs[i] = cg[i];
    }
    __syncthreads();

    unsigned long long acc[NCUE][2];
#pragma unroll
    for (int c = 0; c < NCUE; c++) { acc[c][0] = 0ull; acc[c][1] = 0ull; }

    const unsigned rbase = sb0 + (unsigned)(t * 64);
    const int      sw    = (t >> 1) & 3;
    const unsigned cbase = (unsigned)__cvta_generic_to_shared(cue_sm);

    for (int s = 0; s < NS; s++) {
        if (s < NS - 2)       asm volatile("cp.async.wait_group 2;" ::: "memory");
        else if (s == NS - 2) asm volatile("cp.async.wait_group 1;" ::: "memory");
        else                  asm volatile("cp.async.wait_group 0;" ::: "memory");
        __syncwarp();                       // all lanes' copies of stage s visible

        const unsigned bo = (unsigned)((s & (NBUF - 1)) * STAGE_B);
        const unsigned cb = cbase + (unsigned)(s * DC * 4);
#pragma unroll
        for (int j = 0; j < F4ROW; j++) {
            unsigned long long plo, phi;
            lds_v2u64(plo, phi, rbase + bo + (unsigned)(((j ^ sw) * 16)));
#pragma unroll
            for (int c = 0; c < NCUE; c++) {
                unsigned long long qlo, qhi;
                lds_v2u64(qlo, qhi, cb + (unsigned)(c * D * 4 + j * 16));
                fma2(acc[c][0], plo, qlo);
                fma2(acc[c][1], phi, qhi);
            }
        }
        __syncwarp();                       // reads done before ring reuse
        if (s + 3 < NS) ISSUE_STAGE(s + 3);
    }
#undef ISSUE_STAGE

    // finalize: per-thread sim -> packed key -> warp/block/global max
    const int pidx = min(p0 + t, NPATCH - 1);
    const unsigned lowbits = 0xFFFFFFFFu - (unsigned)pidx;
    unsigned long long key[NCUE];
#pragma unroll
    for (int c = 0; c < NCUE; c++) {
        float a0 = __uint_as_float((unsigned)(acc[c][0] & 0xFFFFFFFFull));
        float a1 = __uint_as_float((unsigned)(acc[c][0] >> 32));
        float a2 = __uint_as_float((unsigned)(acc[c][1] & 0xFFFFFFFFull));
        float a3 = __uint_as_float((unsigned)(acc[c][1] >> 32));
        float sim = (a0 + a1) + (a2 + a3);
        key[c] = ((unsigned long long)f2key(sim) << 32) | lowbits;
    }
#pragma unroll
    for (int c = 0; c < NCUE; c++)
#pragma unroll
        for (int o = 16; o; o >>= 1) {
            unsigned long long other = __shfl_xor_sync(0xffffffffu, key[c], o);
            key[c] = (other > key[c]) ? other : key[c];
        }
    if (lane == 0)
#pragma unroll
        for (int c = 0; c < NCUE; c++) warp_best[warp][c] = key[c];
    __syncthreads();
    if (t < NCUE) {
        unsigned long long m = warp_best[0][t];
#pragma unroll
        for (int w = 1; w < TPB / 32; w++)
            m = (warp_best[w][t] > m) ? warp_best[w][t] : m;
        atomicMax(&g_best[b * NCUE + t], m);
    }
}

// ---------------------------------------------------------------------------
// Kernel 2 (R5 version, measured 9.15us): build + normalize 10 output tokens
// per batch; fully unrolled masked 3x3 ROI (27 independent loads); resets
// g_best for the next replay.
// ---------------------------------------------------------------------------
__global__ __launch_bounds__(256) void gather_kernel(const float* __restrict__ tokens,
                                                     float* __restrict__ out) {
    const int tk = blockIdx.x;
    const int b  = blockIdx.y;
    const float* base = tokens + (size_t)b * STOK * D;
    const int tid = threadIdx.x;

    float v[3];

    if (tk < NCUE) {
        const float* row = base + (size_t)tk * D;
#pragma unroll
        for (int j = 0; j < 3; j++) v[j] = row[tid + 256 * j];
    } else {
        const int c = tk - NCUE;
        const unsigned long long key = g_best[b * NCUE + c];
        const int idx = (int)(0xFFFFFFFFu - (unsigned)(key & 0xFFFFFFFFull));
        const int h = idx / G, w = idx % G;

        const float* prow[9];
        float        msk[9];
        float        cnt = 0.0f;
#pragma unroll
        for (int dr = -1; dr <= 1; dr++)
#pragma unroll
            for (int dc = -1; dc <= 1; dc++) {
                const int k  = (dr + 1) * 3 + (dc + 1);
                const int rr = h + dr, cc = w + dc;
                const bool ok = (rr >= 0) & (rr < G) & (cc >= 0) & (cc < G);
                const int rcl = min(max(rr, 0), G - 1);
                const int ccl = min(max(cc, 0), G - 1);
                prow[k] = base + (size_t)(NCUE + rcl * G + ccl) * D;
                msk[k]  = ok ? 1.0f : 0.0f;
                cnt += msk[k];
            }
        const float inv = 1.0f / cnt;
#pragma unroll
        for (int j = 0; j < 3; j++) v[j] = 0.0f;
#pragma unroll
        for (int k = 0; k < 9; k++) {
#pragma unroll
            for (int j = 0; j < 3; j++)
                v[j] = fmaf(msk[k], prow[k][tid + 256 * j], v[j]);
        }
#pragma unroll
        for (int j = 0; j < 3; j++) v[j] *= inv;
    }

    // block reduce sum of squares
    float ss = v[0] * v[0] + v[1] * v[1] + v[2] * v[2];
#pragma unroll
    for (int o = 16; o > 0; o >>= 1) ss += __shfl_xor_sync(0xffffffffu, ss, o);

    __shared__ float red[8];
    const int lane = tid & 31, warp = tid >> 5;
    if (lane == 0) red[warp] = ss;
    __syncthreads();   // also orders g_best reads before the reset below
    if (warp == 0) {
        float s2 = (lane < 8) ? red[lane] : 0.0f;
        s2 += __shfl_xor_sync(0xffffffffu, s2, 4);
        s2 += __shfl_xor_sync(0xffffffffu, s2, 2);
        s2 += __shfl_xor_sync(0xffffffffu, s2, 1);
        if (lane == 0) red[0] = s2;
    }
    // reset scratch for next replay (exactly one block owns each slot)
    if (tk >= NCUE && tid == 0) g_best[b * NCUE + (tk - NCUE)] = 0ull;
    __syncthreads();

    const float norm  = sqrtf(red[0]);
    const float scale = 1.0f / fmaxf(norm, EPSN);

    float* orow = out + ((size_t)b * 10 + tk) * D;
#pragma unroll
    for (int j = 0; j < 3; j++) orow[tid + 256 * j] = v[j] * scale;
}

extern "C" void kernel_launch(void* const* d_in, const int* in_sizes, int n_in,
                              void* d_out, int out_size) {
    const float* tokens = (const float*)d_in[0];
    float* out = (float*)d_out;

    argmax_kernel<<<dim3(NTILE, BATCH), TPB>>>(tokens);
    gather_kernel<<<dim3(10, BATCH), 256>>>(tokens, out);
}